// round 10
// baseline (speedup 1.0000x reference)
#include <cuda_runtime.h>
#include <cuda.h>
#include <cuda_fp16.h>
#include <cstdint>

#define DIM      4096
#define NPAIRS   2048
#define GRD      64
#define P_TILE   8
#define THREADS  1024
#define SLOTS    4
#define BSTEP    (THREADS / SLOTS)               // 256 rows per iteration
#define GRID_ELEMS (GRD * GRD)
#define GRID_SMEM  (P_TILE * GRID_ELEMS * 4)     // 128 KB fp16 dup-pair grid
#define XDEPTH   4
#define XSTAGE   (BSTEP * 64)                    // 16 KB: 256 rows x 64B (16 floats)
#define OSTAGE   (BSTEP * 32)                    // 8 KB: 256 rows x 32B (8 floats)
#define XRING_OFF  GRID_SMEM                     // 128 KB
#define ORING_OFF  (GRID_SMEM + XDEPTH * XSTAGE) // 192 KB
#define MBAR_OFF   (ORING_OFF + 2 * OSTAGE)      // 208 KB (128B-aligned)
#define SMEM_BYTES (MBAR_OFF + 128)

__device__ __forceinline__ void mbar_init(uint64_t* bar, uint32_t cnt) {
    uint32_t a = (uint32_t)__cvta_generic_to_shared(bar);
    asm volatile("mbarrier.init.shared.b64 [%0], %1;" :: "r"(a), "r"(cnt) : "memory");
}
__device__ __forceinline__ void mbar_expect_tx(uint64_t* bar, uint32_t bytes) {
    uint32_t a = (uint32_t)__cvta_generic_to_shared(bar);
    asm volatile("mbarrier.arrive.expect_tx.shared.b64 _, [%0], %1;"
                 :: "r"(a), "r"(bytes) : "memory");
}
__device__ __forceinline__ void mbar_wait(uint64_t* bar, uint32_t phase) {
    uint32_t a = (uint32_t)__cvta_generic_to_shared(bar);
    asm volatile(
        "{\n\t.reg .pred P;\n\t"
        "WL%=:\n\t"
        "mbarrier.try_wait.parity.acquire.cta.shared::cta.b64 P, [%0], %1, 0x989680;\n\t"
        "@P bra.uni WD%=;\n\t"
        "bra.uni WL%=;\n\t"
        "WD%=:\n\t}"
        :: "r"(a), "r"(phase) : "memory");
}
__device__ __forceinline__ void tma_load_2d(void* smem_dst, const CUtensorMap* map,
                                            int cx, int cy, uint64_t* bar) {
    uint32_t d = (uint32_t)__cvta_generic_to_shared(smem_dst);
    uint32_t b = (uint32_t)__cvta_generic_to_shared(bar);
    asm volatile(
        "cp.async.bulk.tensor.2d.shared::cta.global.tile.mbarrier::complete_tx::bytes "
        "[%0], [%1, {%2, %3}], [%4];"
        :: "r"(d), "l"(map), "r"(cx), "r"(cy), "r"(b) : "memory");
}
__device__ __forceinline__ void tma_store_2d(const CUtensorMap* map,
                                             int cx, int cy, const void* smem_src) {
    uint32_t s = (uint32_t)__cvta_generic_to_shared(smem_src);
    asm volatile(
        "cp.async.bulk.tensor.2d.global.shared::cta.tile.bulk_group "
        "[%0, {%1, %2}], [%3];"
        :: "l"(map), "r"(cx), "r"(cy), "r"(s) : "memory");
}

extern __shared__ __align__(128) char smem[];

__global__ void __launch_bounds__(THREADS, 1)
pair_bilinear_kernel(const __grid_constant__ CUtensorMap tmx,
                     const __grid_constant__ CUtensorMap tmo,
                     const float* __restrict__ pairW,
                     const float* __restrict__ Y,
                     int b_tile, int iters)
{
    __half2* sY = reinterpret_cast<__half2*>(smem);       // dup-pair grid
    uint64_t* mbar = reinterpret_cast<uint64_t*>(smem + MBAR_OFF);

    const int tid = threadIdx.x;
    const int p0 = blockIdx.x * P_TILE;
    const int rowbase = blockIdx.y * b_tile;

    // ── mbarrier init + TMA prologue (stages 0..XDEPTH-2) ────────────────
    if (tid == 0) {
        #pragma unroll
        for (int d = 0; d < XDEPTH; d++) mbar_init(&mbar[d], 1);
        asm volatile("fence.proxy.async.shared::cta;" ::: "memory");
        #pragma unroll
        for (int d = 0; d < XDEPTH - 1; d++) {
            mbar_expect_tx(&mbar[d], XSTAGE);
            tma_load_2d(smem + XRING_OFF + d * XSTAGE, &tmx,
                        2 * p0, rowbase + d * BSTEP, &mbar[d]);
        }
    }

    // ── Stage duplicated-pair fp16 grid (overlaps TMA prologue) ──────────
    {
        const float4* __restrict__ Yg =
            reinterpret_cast<const float4*>(Y) + p0 * (GRID_ELEMS / 4);
        uint4* __restrict__ sY4 = reinterpret_cast<uint4*>(sY);
        #pragma unroll
        for (int i = tid; i < P_TILE * GRID_ELEMS / 4; i += THREADS) {
            const float4 v = Yg[i];
            const int c4 = i & 15;
            const float vnext = (c4 < 15) ? *reinterpret_cast<const float*>(Yg + i + 1)
                                          : v.w;   // cell 63 never read
            __half2 h[4];
            h[0] = __floats2half2_rn(v.x, v.y);
            h[1] = __floats2half2_rn(v.y, v.z);
            h[2] = __floats2half2_rn(v.z, v.w);
            h[3] = __floats2half2_rn(v.w, vnext);
            sY4[i] = *reinterpret_cast<const uint4*>(h);
        }
    }

    const int sl = tid & (SLOTS - 1);            // 0..3 -> pairs 2sl, 2sl+1
    const int bs = tid >> 2;                     // 0..255
    const int pA = p0 + 2 * sl;

    const float4 wA = *(reinterpret_cast<const float4*>(pairW) + pA);
    const float4 wB = *(reinterpret_cast<const float4*>(pairW) + pA + 1);

    const __half2* __restrict__ sA = sY + (2 * sl) * GRID_ELEMS;
    const __half2* __restrict__ sB = sA + GRID_ELEMS;

    __syncthreads();   // grid staged, mbarriers visible to all

    for (int k = 0; k < iters; ++k) {
        // issue x stage k+XDEPTH-1; reclaim out buffer (k & 1)
        if (tid == 0) {
            const int s = k + XDEPTH - 1;
            if (s < iters) {
                mbar_expect_tx(&mbar[s & (XDEPTH - 1)], XSTAGE);
                tma_load_2d(smem + XRING_OFF + (s & (XDEPTH - 1)) * XSTAGE, &tmx,
                            2 * p0, rowbase + s * BSTEP, &mbar[s & (XDEPTH - 1)]);
            }
            if (k >= 2)
                asm volatile("cp.async.bulk.wait_group.read 1;" ::: "memory");
        }
        __syncthreads();                          // out buffer free for all

        mbar_wait(&mbar[k & (XDEPTH - 1)], (k >> 2) & 1);   // x stage k resident

        // x: one conflict-free LDS.128 per thread
        const float4 xv = *reinterpret_cast<const float4*>(
            smem + XRING_OFF + (k & (XDEPTH - 1)) * XSTAGE + bs * 64 + sl * 16);

        const float a0 = fmaf(xv.x, wA.x, xv.y * wA.z);
        const float a1 = fmaf(xv.x, wA.y, xv.y * wA.w);
        const float b0 = fmaf(xv.z, wB.x, xv.w * wB.z);
        const float b1 = fmaf(xv.z, wB.y, xv.w * wB.w);

        const float gA0 = fminf(fmaxf(a0 * 63.0f, 0.0f), 63.0f);
        const float gA1 = fminf(fmaxf(a1 * 63.0f, 0.0f), 63.0f);
        const float gB0 = fminf(fmaxf(b0 * 63.0f, 0.0f), 63.0f);
        const float gB1 = fminf(fmaxf(b1 * 63.0f, 0.0f), 63.0f);

        const int rA = min((int)gA0, 62), cA = min((int)gA1, 62);
        const int rB = min((int)gB0, 62), cB = min((int)gB1, 62);
        const float frA = gA0 - (float)rA, fcA = gA1 - (float)cA;
        const float frB = gB0 - (float)rB, fcB = gB1 - (float)cB;

        const int baseA = (rA << 6) + cA;
        const int baseB = (rB << 6) + cB;
        const __half2 tAh = sA[baseA], bAh = sA[baseA + GRD];
        const __half2 tBh = sB[baseB], bBh = sB[baseB + GRD];

        const float2 ta = __half22float2(tAh);
        const float2 ba = __half22float2(bAh);
        const float2 tb = __half22float2(tBh);
        const float2 bb = __half22float2(bBh);

        const float topA = fmaf(fcA, ta.y - ta.x, ta.x);
        const float botA = fmaf(fcA, ba.y - ba.x, ba.x);
        const float topB = fmaf(fcB, tb.y - tb.x, tb.x);
        const float botB = fmaf(fcB, bb.y - bb.x, bb.x);

        float2 o;
        o.x = fmaf(frA, botA - topA, topA);
        o.y = fmaf(frB, botB - topB, topB);
        *reinterpret_cast<float2*>(
            smem + ORING_OFF + (k & 1) * OSTAGE + bs * 32 + sl * 8) = o;

        __syncthreads();                          // out tile complete

        if (tid == 0) {
            asm volatile("fence.proxy.async.shared::cta;" ::: "memory");
            tma_store_2d(&tmo, p0, rowbase + k * BSTEP,
                         smem + ORING_OFF + (k & 1) * OSTAGE);
            asm volatile("cp.async.bulk.commit_group;" ::: "memory");
        }
    }

    if (tid == 0)
        asm volatile("cp.async.bulk.wait_group 0;" ::: "memory");
}

extern "C" void kernel_launch(void* const* d_in, const int* in_sizes, int n_in,
                              void* d_out, int out_size)
{
    const float* pairW = (const float*)d_in[1];
    const float* Y     = (const float*)d_in[2];

    const int batch = in_sizes[0] / DIM;   // 8192

    // ── build tensor maps via runtime-resolved driver entry point ────────
    typedef CUresult (*EncodeFn)(CUtensorMap*, CUtensorMapDataType, cuuint32_t, void*,
                                 const cuuint64_t*, const cuuint64_t*,
                                 const cuuint32_t*, const cuuint32_t*,
                                 CUtensorMapInterleave, CUtensorMapSwizzle,
                                 CUtensorMapL2promotion, CUtensorMapFloatOOBfill);
    void* sym = nullptr;
    cudaDriverEntryPointQueryResult qr;
    cudaGetDriverEntryPoint("cuTensorMapEncodeTiled", &sym, cudaEnableDefault, &qr);
    EncodeFn enc = (EncodeFn)sym;

    alignas(64) CUtensorMap tmx, tmo;
    {
        cuuint64_t dims[2]    = {(cuuint64_t)DIM, (cuuint64_t)batch};
        cuuint64_t strides[1] = {(cuuint64_t)DIM * 4};
        cuuint32_t box[2]     = {16, BSTEP};          // 64B x 256 rows
        cuuint32_t es[2]      = {1, 1};
        enc(&tmx, CU_TENSOR_MAP_DATA_TYPE_FLOAT32, 2, (void*)d_in[0],
            dims, strides, box, es,
            CU_TENSOR_MAP_INTERLEAVE_NONE, CU_TENSOR_MAP_SWIZZLE_NONE,
            CU_TENSOR_MAP_L2_PROMOTION_L2_128B, CU_TENSOR_MAP_FLOAT_OOB_FILL_NONE);
    }
    {
        cuuint64_t dims[2]    = {(cuuint64_t)NPAIRS, (cuuint64_t)batch};
        cuuint64_t strides[1] = {(cuuint64_t)NPAIRS * 4};
        cuuint32_t box[2]     = {P_TILE, BSTEP};      // 32B x 256 rows
        cuuint32_t es[2]      = {1, 1};
        enc(&tmo, CU_TENSOR_MAP_DATA_TYPE_FLOAT32, 2, d_out,
            dims, strides, box, es,
            CU_TENSOR_MAP_INTERLEAVE_NONE, CU_TENSOR_MAP_SWIZZLE_NONE,
            CU_TENSOR_MAP_L2_PROMOTION_L2_128B, CU_TENSOR_MAP_FLOAT_OOB_FILL_NONE);
    }

    const int b_blocks = 4;
    const int b_tile = batch / b_blocks;               // 2048
    const int iters  = b_tile / BSTEP;                 // 8

    cudaFuncSetAttribute(pair_bilinear_kernel,
                         cudaFuncAttributeMaxDynamicSharedMemorySize, SMEM_BYTES);

    dim3 grid(NPAIRS / P_TILE, b_blocks);   // (256, 4)
    pair_bilinear_kernel<<<grid, THREADS, SMEM_BYTES>>>(tmx, tmo, pairW, Y,
                                                        b_tile, iters);
}

// round 11
// speedup vs baseline: 1.4776x; 1.4776x over previous
#include <cuda_runtime.h>
#include <cuda_fp16.h>
#include <cstdint>

#define DIM      4096
#define NPAIRS   2048
#define GRD      64
#define P_TILE   8                               // pairs staged per block
#define THREADS  1024
#define SLOTS    4                               // pair-slots (2 pairs each)
#define BSTEP    (THREADS / SLOTS)               // 256 batch rows per iter
#define GRID_ELEMS (GRD * GRD)                   // 4096 cells per pair
#define SMEM_BYTES (P_TILE * GRID_ELEMS * 4)     // 128 KB (half2 dup-pair cells)
#define GSIZE    2                               // iterations per pipeline group

__global__ void __launch_bounds__(THREADS, 1)
pair_bilinear_kernel(const float* __restrict__ x,
                     const float* __restrict__ pairW,
                     const float* __restrict__ Y,
                     float* __restrict__ out,
                     int groups)
{
    extern __shared__ __half2 sY[];  // [P_TILE][64][64] : cell = {Y[r][c], Y[r][c+1]}

    const int p0 = blockIdx.x * P_TILE;
    const int tid = threadIdx.x;

    const int sl = tid & (SLOTS - 1);    // pair-slot (0..3) -> pairs 2sl,2sl+1
    const int bs = tid >> 2;             // batch sub-index (0..255)
    const int pA = p0 + 2 * sl;          // first pair of this thread

    // x: 4 consecutive floats per (b, slot) -> one float4
    const float4* __restrict__ xp =
        reinterpret_cast<const float4*>(x) + (size_t)bs * (DIM / 4) + (pA >> 1);
    const int XSTR = BSTEP * (DIM / 4);

    // ── Hoisted first x-group prefetch: overlaps Y staging below ─────────
    float4 xa[GSIZE];
    #pragma unroll
    for (int i = 0; i < GSIZE; i++) xa[i] = xp[i * XSTR];
    xp += GSIZE * XSTR;

    // ── Stage: duplicated-pair fp16 grid from fp32 Y (once per block) ────
    {
        const float4* __restrict__ Yg =
            reinterpret_cast<const float4*>(Y) + p0 * (GRID_ELEMS / 4);
        uint4* __restrict__ sY4 = reinterpret_cast<uint4*>(sY);
        #pragma unroll
        for (int i = tid; i < P_TILE * GRID_ELEMS / 4; i += THREADS) {
            const float4 v = Yg[i];
            const int c4 = i & 15;               // float4 index within 64-wide row
            const float vnext = (c4 < 15) ? *reinterpret_cast<const float*>(Yg + i + 1)
                                          : v.w;  // cell 63 never read
            __half2 h[4];
            h[0] = __floats2half2_rn(v.x, v.y);
            h[1] = __floats2half2_rn(v.y, v.z);
            h[2] = __floats2half2_rn(v.z, v.w);
            h[3] = __floats2half2_rn(v.w, vnext);
            sY4[i] = *reinterpret_cast<const uint4*>(h);   // STS.128, conflict-free
        }
    }
    __syncthreads();

    const float4 wA = *(reinterpret_cast<const float4*>(pairW) + pA);
    const float4 wB = *(reinterpret_cast<const float4*>(pairW) + pA + 1);

    const __half2* __restrict__ sA = sY + (2 * sl) * GRID_ELEMS;
    const __half2* __restrict__ sB = sA + GRID_ELEMS;

    float2* __restrict__ op =
        reinterpret_cast<float2*>(out + (size_t)bs * NPAIRS + pA);
    const int OSTR = BSTEP * (NPAIRS / 2);

    // ── Software-pipelined main loop (16 groups, whole batch) ────────────
    for (int gset = 0; gset < groups; ++gset) {
        float4 xb[GSIZE];
        if (gset + 1 < groups) {
            #pragma unroll
            for (int i = 0; i < GSIZE; i++) xb[i] = xp[i * XSTR];
            xp += GSIZE * XSTR;
        }

        __half2 tA[GSIZE], bA[GSIZE], tB[GSIZE], bB[GSIZE];
        float frA[GSIZE], fcA[GSIZE], frB[GSIZE], fcB[GSIZE];

        // Phase A: addresses + all 4*GSIZE gathers in flight
        #pragma unroll
        for (int i = 0; i < GSIZE; i++) {
            const float a0 = fmaf(xa[i].x, wA.x, xa[i].y * wA.z);
            const float a1 = fmaf(xa[i].x, wA.y, xa[i].y * wA.w);
            const float b0 = fmaf(xa[i].z, wB.x, xa[i].w * wB.z);
            const float b1 = fmaf(xa[i].z, wB.y, xa[i].w * wB.w);

            const float gA0 = fminf(fmaxf(a0 * 63.0f, 0.0f), 63.0f);
            const float gA1 = fminf(fmaxf(a1 * 63.0f, 0.0f), 63.0f);
            const float gB0 = fminf(fmaxf(b0 * 63.0f, 0.0f), 63.0f);
            const float gB1 = fminf(fmaxf(b1 * 63.0f, 0.0f), 63.0f);

            const int rA = min((int)gA0, 62), cA = min((int)gA1, 62);
            const int rB = min((int)gB0, 62), cB = min((int)gB1, 62);
            frA[i] = gA0 - (float)rA;  fcA[i] = gA1 - (float)cA;
            frB[i] = gB0 - (float)rB;  fcB[i] = gB1 - (float)cB;

            const int baseA = (rA << 6) + cA;
            const int baseB = (rB << 6) + cB;
            tA[i] = sA[baseA];  bA[i] = sA[baseA + GRD];
            tB[i] = sB[baseB];  bB[i] = sB[baseB + GRD];
        }

        // Phase B: blend + vectorized store
        #pragma unroll
        for (int i = 0; i < GSIZE; i++) {
            const float2 ta = __half22float2(tA[i]);
            const float2 ba = __half22float2(bA[i]);
            const float2 tb = __half22float2(tB[i]);
            const float2 bb = __half22float2(bB[i]);

            const float topA = fmaf(fcA[i], ta.y - ta.x, ta.x);
            const float botA = fmaf(fcA[i], ba.y - ba.x, ba.x);
            const float topB = fmaf(fcB[i], tb.y - tb.x, tb.x);
            const float botB = fmaf(fcB[i], bb.y - bb.x, bb.x);

            float2 o;
            o.x = fmaf(frA[i], botA - topA, topA);
            o.y = fmaf(frB[i], botB - topB, topB);
            *op = o;                             // STG.64
            op += OSTR;
        }

        #pragma unroll
        for (int i = 0; i < GSIZE; i++) xa[i] = xb[i];
    }
}

extern "C" void kernel_launch(void* const* d_in, const int* in_sizes, int n_in,
                              void* d_out, int out_size)
{
    const float* x     = (const float*)d_in[0];
    const float* pairW = (const float*)d_in[1];
    const float* Y     = (const float*)d_in[2];
    float* out         = (float*)d_out;

    const int batch = in_sizes[0] / DIM;               // 8192
    const int groups = batch / (GSIZE * BSTEP);        // 8192 / 512 = 16

    cudaFuncSetAttribute(pair_bilinear_kernel,
                         cudaFuncAttributeMaxDynamicSharedMemorySize, SMEM_BYTES);

    dim3 grid(NPAIRS / P_TILE, 1);   // 256 persistent pair-tile blocks
    pair_bilinear_kernel<<<grid, THREADS, SMEM_BYTES>>>(x, pairW, Y, out, groups);
}